// round 1
// baseline (speedup 1.0000x reference)
#include <cuda_runtime.h>
#include <math.h>

#define N_NODES 49998
#define E_EDGES 800000
#define DIN 128
#define NH0 8
#define DOUT 32
#define F0 (NH0 * DOUT)   // 256
#define F1 32
#define NE_PAIRS (N_NODES / 3)  // 16666
#define FULLMASK 0xffffffffu

// ---------------- scratch (device globals: no runtime alloc allowed) ----------------
__device__ float g_f0[N_NODES * F0];     // layer0 projected features
__device__ float g_h[N_NODES * F0];      // elu(gat0 out)
__device__ float g_el0[N_NODES * NH0];
__device__ float g_er0[N_NODES * NH0];
__device__ float g_f1[N_NODES * F1];
__device__ float g_el1[N_NODES];
__device__ float g_er1[N_NODES];
__device__ float g_h1[N_NODES * F1];
__device__ int   g_cnt[N_NODES];
__device__ int   g_rowptr[N_NODES + 1];
__device__ int   g_esrc[E_EDGES];        // src ids sorted by dst (CSR)

// ---------------- CSR build ----------------
__global__ void k_zero_cnt() {
    int i = blockIdx.x * blockDim.x + threadIdx.x;
    if (i < N_NODES) g_cnt[i] = 0;
}

__global__ void k_count(const int* __restrict__ dst) {
    int e = blockIdx.x * blockDim.x + threadIdx.x;
    if (e < E_EDGES) atomicAdd(&g_cnt[dst[e]], 1);
}

__global__ void k_scan() {
    const int T = 1024;
    int tid = threadIdx.x;
    int chunk = (N_NODES + T - 1) / T;
    int beg = tid * chunk;
    int end = beg + chunk; if (end > N_NODES) end = N_NODES;
    int s = 0;
    for (int i = beg; i < end; i++) s += g_cnt[i];
    __shared__ int sh[T];
    sh[tid] = s;
    __syncthreads();
    for (int d = 1; d < T; d <<= 1) {
        int v = (tid >= d) ? sh[tid - d] : 0;
        __syncthreads();
        sh[tid] += v;
        __syncthreads();
    }
    int run = sh[tid] - s;  // exclusive prefix
    for (int i = beg; i < end; i++) { g_rowptr[i] = run; run += g_cnt[i]; }
    if (tid == T - 1) g_rowptr[N_NODES] = sh[T - 1];
}

__global__ void k_fill(const int* __restrict__ src, const int* __restrict__ dst) {
    int e = blockIdx.x * blockDim.x + threadIdx.x;
    if (e < E_EDGES) {
        int d = dst[e];
        int p = atomicAdd(&g_cnt[d], 1);
        g_esrc[g_rowptr[d] + p] = src[e];
    }
}

// ---------------- register-tiled fp32 GEMM: C(MxNc) = A(MxK) @ B(KxNc) ----------------
template <int BM, int BN, int BK, int TM, int TN>
__global__ void k_gemm(const float* __restrict__ A, const float* __restrict__ B,
                       float* __restrict__ C, int M, int Nc, int K) {
    __shared__ float As[BK][BM + 1];
    __shared__ float Bs[BK][BN];
    const int NTH = (BM / TM) * (BN / TN);
    const int tx = threadIdx.x % (BN / TN);
    const int ty = threadIdx.x / (BN / TN);
    const int row0 = blockIdx.y * BM;
    const int col0 = blockIdx.x * BN;

    float acc[TM][TN];
#pragma unroll
    for (int i = 0; i < TM; i++)
#pragma unroll
        for (int j = 0; j < TN; j++) acc[i][j] = 0.f;

    for (int k0 = 0; k0 < K; k0 += BK) {
        for (int i = threadIdx.x; i < BM * BK; i += NTH) {
            int r = i / BK, c = i % BK;
            int gr = row0 + r;
            As[c][r] = (gr < M) ? A[(long)gr * K + k0 + c] : 0.f;
        }
        for (int i = threadIdx.x; i < BK * BN; i += NTH) {
            int r = i / BN, c = i % BN;
            Bs[r][c] = B[(long)(k0 + r) * Nc + col0 + c];
        }
        __syncthreads();
#pragma unroll
        for (int k = 0; k < BK; k++) {
            float a[TM], b[TN];
#pragma unroll
            for (int i = 0; i < TM; i++) a[i] = As[k][ty * TM + i];
#pragma unroll
            for (int j = 0; j < TN; j++) b[j] = Bs[k][tx * TN + j];
#pragma unroll
            for (int i = 0; i < TM; i++)
#pragma unroll
                for (int j = 0; j < TN; j++) acc[i][j] += a[i] * b[j];
        }
        __syncthreads();
    }
#pragma unroll
    for (int i = 0; i < TM; i++) {
        int gr = row0 + ty * TM + i;
        if (gr < M) {
#pragma unroll
            for (int j = 0; j < TN; j++)
                C[(long)gr * Nc + col0 + tx * TN + j] = acc[i][j];
        }
    }
}

// ---------------- attention logits el/er ----------------
__global__ void k_scores0(const float* __restrict__ al, const float* __restrict__ ar) {
    int n = blockIdx.x;
    int t = threadIdx.x;              // 256 = h*32 + d
    int h = t >> 5, d = t & 31;
    float f = g_f0[n * F0 + t];
    float el = f * al[t];
    float er = f * ar[t];
#pragma unroll
    for (int o = 16; o; o >>= 1) {
        el += __shfl_xor_sync(FULLMASK, el, o);
        er += __shfl_xor_sync(FULLMASK, er, o);
    }
    if (d == 0) {
        g_el0[n * NH0 + h] = el;
        g_er0[n * NH0 + h] = er;
    }
}

__global__ void k_scores1(const float* __restrict__ al, const float* __restrict__ ar) {
    int g = blockIdx.x * blockDim.x + threadIdx.x;
    int n = g >> 5, lane = g & 31;
    if (n >= N_NODES) return;
    float f = g_f1[n * F1 + lane];
    float el = f * al[lane];
    float er = f * ar[lane];
#pragma unroll
    for (int o = 16; o; o >>= 1) {
        el += __shfl_xor_sync(FULLMASK, el, o);
        er += __shfl_xor_sync(FULLMASK, er, o);
    }
    if (lane == 0) { g_el1[n] = el; g_er1[n] = er; }
}

// ---------------- layer-0 aggregation: warp per dst node, 8 heads x 32 dims ----------------
__global__ void k_agg0(const float* __restrict__ b0) {
    int g = blockIdx.x * blockDim.x + threadIdx.x;
    int n = g >> 5, lane = g & 31;
    if (n >= N_NODES) return;
    int beg = g_rowptr[n], end = g_rowptr[n + 1];
    int deg = end - beg;

    float er[NH0];
#pragma unroll
    for (int h = 0; h < NH0; h++) er[h] = g_er0[n * NH0 + h];

    // pass 1: per-head max (softmax stabilization)
    float m[NH0];
#pragma unroll
    for (int h = 0; h < NH0; h++) m[h] = -INFINITY;
    for (int i = lane; i < deg; i += 32) {
        int s = g_esrc[beg + i];
        const float4* elp = (const float4*)&g_el0[s * NH0];
        float4 e0 = elp[0], e1 = elp[1];
        float ev[NH0] = {e0.x, e0.y, e0.z, e0.w, e1.x, e1.y, e1.z, e1.w};
#pragma unroll
        for (int h = 0; h < NH0; h++) {
            float e = ev[h] + er[h];
            e = (e > 0.f) ? e : 0.2f * e;
            m[h] = fmaxf(m[h], e);
        }
    }
#pragma unroll
    for (int h = 0; h < NH0; h++)
#pragma unroll
        for (int o = 16; o; o >>= 1) m[h] = fmaxf(m[h], __shfl_xor_sync(FULLMASK, m[h], o));

    // pass 2: unnormalized weighted sum + Σexp
    float acc[NH0], ssum[NH0];
#pragma unroll
    for (int h = 0; h < NH0; h++) { acc[h] = 0.f; ssum[h] = 0.f; }

    for (int base = 0; base < deg; base += 32) {
        int i = base + lane;
        int s = 0;
        float w[NH0];
#pragma unroll
        for (int h = 0; h < NH0; h++) w[h] = 0.f;
        if (i < deg) {
            s = g_esrc[beg + i];
            const float4* elp = (const float4*)&g_el0[s * NH0];
            float4 e0 = elp[0], e1 = elp[1];
            float ev[NH0] = {e0.x, e0.y, e0.z, e0.w, e1.x, e1.y, e1.z, e1.w};
#pragma unroll
            for (int h = 0; h < NH0; h++) {
                float e = ev[h] + er[h];
                e = (e > 0.f) ? e : 0.2f * e;
                float ww = __expf(e - m[h]);
                w[h] = ww;
                ssum[h] += ww;
            }
        }
        int cnt = deg - base; if (cnt > 32) cnt = 32;
        for (int j = 0; j < cnt; j++) {
            int sj = __shfl_sync(FULLMASK, s, j);
            const float* frow = &g_f0[sj * F0 + lane];
#pragma unroll
            for (int h = 0; h < NH0; h++) {
                float wj = __shfl_sync(FULLMASK, w[h], j);
                acc[h] += wj * frow[h * 32];
            }
        }
    }
#pragma unroll
    for (int h = 0; h < NH0; h++)
#pragma unroll
        for (int o = 16; o; o >>= 1) ssum[h] += __shfl_xor_sync(FULLMASK, ssum[h], o);

    // normalize, + bias, elu, store
#pragma unroll
    for (int h = 0; h < NH0; h++) {
        float v = (deg > 0) ? (acc[h] / ssum[h]) : 0.f;
        v += b0[h * 32 + lane];
        v = (v > 0.f) ? v : expm1f(v);
        g_h[n * F0 + h * 32 + lane] = v;
    }
}

// ---------------- layer-1 aggregation: warp per dst node, 1 head x 32 dims ----------------
__global__ void k_agg1(const float* __restrict__ b1) {
    int g = blockIdx.x * blockDim.x + threadIdx.x;
    int n = g >> 5, lane = g & 31;
    if (n >= N_NODES) return;
    int beg = g_rowptr[n], end = g_rowptr[n + 1];
    int deg = end - beg;
    float er = g_er1[n];

    float m = -INFINITY;
    for (int i = lane; i < deg; i += 32) {
        int s = g_esrc[beg + i];
        float e = g_el1[s] + er;
        e = (e > 0.f) ? e : 0.2f * e;
        m = fmaxf(m, e);
    }
#pragma unroll
    for (int o = 16; o; o >>= 1) m = fmaxf(m, __shfl_xor_sync(FULLMASK, m, o));

    float acc = 0.f, ssum = 0.f;
    for (int base = 0; base < deg; base += 32) {
        int i = base + lane;
        int s = 0;
        float w = 0.f;
        if (i < deg) {
            s = g_esrc[beg + i];
            float e = g_el1[s] + er;
            e = (e > 0.f) ? e : 0.2f * e;
            w = __expf(e - m);
            ssum += w;
        }
        int cnt = deg - base; if (cnt > 32) cnt = 32;
        for (int j = 0; j < cnt; j++) {
            int sj = __shfl_sync(FULLMASK, s, j);
            float wj = __shfl_sync(FULLMASK, w, j);
            acc += wj * g_f1[sj * F1 + lane];
        }
    }
#pragma unroll
    for (int o = 16; o; o >>= 1) ssum += __shfl_xor_sync(FULLMASK, ssum, o);

    float v = (deg > 0) ? (acc / ssum) : 0.f;
    g_h1[n * F1 + lane] = v + b1[lane];
}

// ---------------- link predictor MLP: warp per pair ----------------
__global__ void k_pred(const float* __restrict__ P1, const float* __restrict__ pb1,
                       const float* __restrict__ P2, const float* __restrict__ pb2,
                       const float* __restrict__ P3, const float* __restrict__ pb3,
                       float* __restrict__ out) {
    __shared__ float sP1[1024], sP2[1024], sP3[32], sb1[32], sb2[32];
    for (int i = threadIdx.x; i < 1024; i += blockDim.x) { sP1[i] = P1[i]; sP2[i] = P2[i]; }
    if (threadIdx.x < 32) {
        sP3[threadIdx.x] = P3[threadIdx.x];
        sb1[threadIdx.x] = pb1[threadIdx.x];
        sb2[threadIdx.x] = pb2[threadIdx.x];
    }
    __syncthreads();

    int g = blockIdx.x * blockDim.x + threadIdx.x;
    int w = g >> 5, lane = g & 31;
    if (w >= 2 * NE_PAIRS) return;
    int neg = (w >= NE_PAIRS) ? 1 : 0;
    int i = w - neg * NE_PAIRS;

    float a = g_h1[i * F1 + lane];
    int dst_row = neg ? (2 * NE_PAIRS + i) : (NE_PAIRS + i);
    float z = a * g_h1[dst_row * F1 + lane];

    // layer 1
    float y = sb1[lane];
#pragma unroll
    for (int d = 0; d < 32; d++) {
        float zd = __shfl_sync(FULLMASK, z, d);
        y += zd * sP1[d * 32 + lane];
    }
    y = fmaxf(y, 0.f);
    // layer 2
    float y2 = sb2[lane];
#pragma unroll
    for (int d = 0; d < 32; d++) {
        float yd = __shfl_sync(FULLMASK, y, d);
        y2 += yd * sP2[d * 32 + lane];
    }
    y2 = fmaxf(y2, 0.f);
    // layer 3 (32 -> 1)
    float t = y2 * sP3[lane];
#pragma unroll
    for (int o = 16; o; o >>= 1) t += __shfl_xor_sync(FULLMASK, t, o);
    if (lane == 0) out[neg * NE_PAIRS + i] = t + pb3[0];
}

// ---------------- launch ----------------
extern "C" void kernel_launch(void* const* d_in, const int* in_sizes, int n_in,
                              void* d_out, int out_size) {
    const float* x   = (const float*)d_in[0];
    const int*   src = (const int*)d_in[1];
    const int*   dst = (const int*)d_in[2];
    // d_in[3] = neg_sample_ratio (fixed = 1)
    const float* W0  = (const float*)d_in[4];
    const float* al0 = (const float*)d_in[5];
    const float* ar0 = (const float*)d_in[6];
    const float* b0  = (const float*)d_in[7];
    const float* W1  = (const float*)d_in[8];
    const float* al1 = (const float*)d_in[9];
    const float* ar1 = (const float*)d_in[10];
    const float* b1  = (const float*)d_in[11];
    const float* P1  = (const float*)d_in[12];
    const float* pb1 = (const float*)d_in[13];
    const float* P2  = (const float*)d_in[14];
    const float* pb2 = (const float*)d_in[15];
    const float* P3  = (const float*)d_in[16];
    const float* pb3 = (const float*)d_in[17];
    float* out = (float*)d_out;

    float *p_f0, *p_h, *p_f1;
    cudaGetSymbolAddress((void**)&p_f0, g_f0);
    cudaGetSymbolAddress((void**)&p_h, g_h);
    cudaGetSymbolAddress((void**)&p_f1, g_f1);

    // CSR by dst
    k_zero_cnt<<<(N_NODES + 255) / 256, 256>>>();
    k_count<<<(E_EDGES + 255) / 256, 256>>>(dst);
    k_scan<<<1, 1024>>>();
    k_zero_cnt<<<(N_NODES + 255) / 256, 256>>>();
    k_fill<<<(E_EDGES + 255) / 256, 256>>>(src, dst);

    // layer 0
    k_gemm<64, 64, 16, 4, 4><<<dim3(F0 / 64, (N_NODES + 63) / 64), 256>>>(x, W0, p_f0, N_NODES, F0, DIN);
    k_scores0<<<N_NODES, 256>>>(al0, ar0);
    k_agg0<<<(N_NODES + 7) / 8, 256>>>(b0);

    // layer 1
    k_gemm<64, 32, 32, 4, 4><<<dim3(1, (N_NODES + 63) / 64), 128>>>(p_h, W1, p_f1, N_NODES, F1, F0);
    k_scores1<<<(N_NODES * 32 + 255) / 256, 256>>>(al1, ar1);
    k_agg1<<<(N_NODES * 32 + 255) / 256, 256>>>(b1);

    // predictor
    k_pred<<<(2 * NE_PAIRS * 32 + 255) / 256, 256>>>(P1, pb1, P2, pb2, P3, pb3, out);
}

// round 2
// speedup vs baseline: 1.3778x; 1.3778x over previous
#include <cuda_runtime.h>
#include <math.h>
#include <stdint.h>

#define N_NODES 49998
#define E_EDGES 800000
#define DIN 128
#define NH0 8
#define DOUT 32
#define F0 (NH0 * DOUT)   // 256
#define F1 32
#define NE_PAIRS (N_NODES / 3)  // 16666
#define FULLMASK 0xffffffffu

// ---------------- scratch (device globals: no runtime alloc allowed) ----------------
__device__ float g_f0[N_NODES * F0];     // layer0 projected features
__device__ float g_h[N_NODES * F0];      // elu(gat0 out)
__device__ float g_el0[N_NODES * NH0];
__device__ float g_er0[N_NODES * NH0];
__device__ float g_f1[N_NODES * F1];
__device__ float g_el1[N_NODES];
__device__ float g_er1[N_NODES];
__device__ float g_h1[N_NODES * F1];
__device__ int   g_cnt[N_NODES];
__device__ int   g_rowptr[N_NODES + 1];
__device__ int   g_esrc[E_EDGES];        // src ids sorted by dst (CSR)

// ---------------- CSR build ----------------
__global__ void k_zero_cnt() {
    int i = blockIdx.x * blockDim.x + threadIdx.x;
    if (i < N_NODES) g_cnt[i] = 0;
}

__global__ void k_count(const int* __restrict__ dst) {
    int e = blockIdx.x * blockDim.x + threadIdx.x;
    if (e < E_EDGES) atomicAdd(&g_cnt[dst[e]], 1);
}

__global__ void k_scan() {
    const int T = 1024;
    int tid = threadIdx.x;
    int chunk = (N_NODES + T - 1) / T;
    int beg = tid * chunk;
    int end = beg + chunk; if (end > N_NODES) end = N_NODES;
    int s = 0;
    for (int i = beg; i < end; i++) s += g_cnt[i];
    __shared__ int sh[T];
    sh[tid] = s;
    __syncthreads();
    for (int d = 1; d < T; d <<= 1) {
        int v = (tid >= d) ? sh[tid - d] : 0;
        __syncthreads();
        sh[tid] += v;
        __syncthreads();
    }
    int run = sh[tid] - s;  // exclusive prefix
    for (int i = beg; i < end; i++) { g_rowptr[i] = run; run += g_cnt[i]; }
    if (tid == T - 1) g_rowptr[N_NODES] = sh[T - 1];
}

__global__ void k_fill(const int* __restrict__ src, const int* __restrict__ dst) {
    int e = blockIdx.x * blockDim.x + threadIdx.x;
    if (e < E_EDGES) {
        int d = dst[e];
        int p = atomicAdd(&g_cnt[d], 1);
        g_esrc[g_rowptr[d] + p] = src[e];
    }
}

// ---------------- tf32 tensor-core GEMM + fused attention scores ----------------
__device__ __forceinline__ uint32_t f2tf(float f) {
    uint32_t r;
    asm("cvt.rna.tf32.f32 %0, %1;" : "=r"(r) : "f"(f));
    return r;
}

__device__ __forceinline__ void mma_tf32(float* d, const uint32_t* a, const uint32_t* b) {
    asm volatile(
        "mma.sync.aligned.m16n8k8.row.col.f32.tf32.tf32.f32 "
        "{%0,%1,%2,%3},{%4,%5,%6,%7},{%8,%9},{%0,%1,%2,%3};\n"
        : "+f"(d[0]), "+f"(d[1]), "+f"(d[2]), "+f"(d[3])
        : "r"(a[0]), "r"(a[1]), "r"(a[2]), "r"(a[3]), "r"(b[0]), "r"(b[1]));
}

// C(MxNc) = A(MxK) @ B(KxNc), tf32 inputs, fp32 accumulate.
// If SCORES: also computes el[r*NH+h] = sum_d C[r, h*32+d]*al[h*32+d] (and er).
// Requires WN == 32 (each warp owns exactly one head's columns) when SCORES.
template <int BM, int BN, int BK, int WM, int WN, int NH, bool SCORES>
__global__ void k_gemm_tf32(const float* __restrict__ A, const float* __restrict__ B,
                            float* __restrict__ C, int M, int Nc, int K,
                            const float* __restrict__ al, const float* __restrict__ ar,
                            float* __restrict__ el, float* __restrict__ er) {
    constexpr int WARPS_M = BM / WM;
    constexpr int WARPS_N = BN / WN;
    constexpr int THREADS = WARPS_M * WARPS_N * 32;
    constexpr int MT = WM / 16;
    constexpr int NT = WN / 8;
    constexpr int AP = BK + 4;   // smem pad: conflict-free fragment reads
    constexpr int BP = BN + 8;

    __shared__ uint32_t As[BM][AP];
    __shared__ uint32_t Bs[BK][BP];

    const int tid = threadIdx.x;
    const int wid = tid >> 5, lane = tid & 31;
    const int wm = (wid / WARPS_N) * WM;
    const int wn = (wid % WARPS_N) * WN;
    const int g = lane >> 2, t = lane & 3;
    const int row0 = blockIdx.y * BM, col0 = blockIdx.x * BN;

    float acc[MT][NT][4];
#pragma unroll
    for (int mt = 0; mt < MT; mt++)
#pragma unroll
        for (int nt = 0; nt < NT; nt++)
#pragma unroll
            for (int j = 0; j < 4; j++) acc[mt][nt][j] = 0.f;

    constexpr int A_CG = BK / 4;               // float4 col-groups in A tile
    constexpr int A_RPP = THREADS / A_CG;      // rows per pass
    constexpr int NB4 = BN / 4;
    constexpr int B_RPP = THREADS / NB4;

    for (int k0 = 0; k0 < K; k0 += BK) {
        // A tile -> smem (tf32)
#pragma unroll
        for (int i = 0; i < BM / A_RPP; i++) {
            int r = (tid / A_CG) + i * A_RPP;
            int c = (tid % A_CG) * 4;
            int gr = row0 + r;
            float4 v = make_float4(0.f, 0.f, 0.f, 0.f);
            if (gr < M) v = *(const float4*)&A[(long)gr * K + k0 + c];
            As[r][c + 0] = f2tf(v.x);
            As[r][c + 1] = f2tf(v.y);
            As[r][c + 2] = f2tf(v.z);
            As[r][c + 3] = f2tf(v.w);
        }
        // B tile -> smem (tf32)
#pragma unroll
        for (int i = 0; i < BK / B_RPP; i++) {
            int r = tid / NB4 + i * B_RPP;
            int c = (tid % NB4) * 4;
            float4 v = *(const float4*)&B[(long)(k0 + r) * Nc + col0 + c];
            Bs[r][c + 0] = f2tf(v.x);
            Bs[r][c + 1] = f2tf(v.y);
            Bs[r][c + 2] = f2tf(v.z);
            Bs[r][c + 3] = f2tf(v.w);
        }
        __syncthreads();

#pragma unroll
        for (int ks = 0; ks < BK / 8; ks++) {
            const int k8 = ks * 8;
            uint32_t af[MT][4], bf[NT][2];
#pragma unroll
            for (int mt = 0; mt < MT; mt++) {
                int r = wm + mt * 16;
                af[mt][0] = As[r + g][k8 + t];
                af[mt][1] = As[r + g + 8][k8 + t];
                af[mt][2] = As[r + g][k8 + t + 4];
                af[mt][3] = As[r + g + 8][k8 + t + 4];
            }
#pragma unroll
            for (int nt = 0; nt < NT; nt++) {
                int c = wn + nt * 8 + g;
                bf[nt][0] = Bs[k8 + t][c];
                bf[nt][1] = Bs[k8 + t + 4][c];
            }
#pragma unroll
            for (int mt = 0; mt < MT; mt++)
#pragma unroll
                for (int nt = 0; nt < NT; nt++) mma_tf32(acc[mt][nt], af[mt], bf[nt]);
        }
        __syncthreads();
    }

    // store C (float2 per fragment row)
#pragma unroll
    for (int mt = 0; mt < MT; mt++) {
#pragma unroll
        for (int nt = 0; nt < NT; nt++) {
            int mr = row0 + wm + mt * 16 + g;
            int c = col0 + wn + nt * 8 + 2 * t;
            if (mr < M)
                *(float2*)&C[(long)mr * Nc + c] = make_float2(acc[mt][nt][0], acc[mt][nt][1]);
            if (mr + 8 < M)
                *(float2*)&C[(long)(mr + 8) * Nc + c] = make_float2(acc[mt][nt][2], acc[mt][nt][3]);
        }
    }

    if (SCORES) {
        const int h = (col0 + wn) >> 5;   // WN == 32: one head per warp
#pragma unroll
        for (int mt = 0; mt < MT; mt++) {
            float elA = 0.f, erA = 0.f;   // row g
            float elB = 0.f, erB = 0.f;   // row g+8
#pragma unroll
            for (int nt = 0; nt < NT; nt++) {
#pragma unroll
                for (int j = 0; j < 2; j++) {
                    int c = nt * 8 + 2 * t + j;   // column within head
                    float av = al[h * 32 + c];
                    float rv = ar[h * 32 + c];
                    elA += acc[mt][nt][j] * av;
                    erA += acc[mt][nt][j] * rv;
                    elB += acc[mt][nt][2 + j] * av;
                    erB += acc[mt][nt][2 + j] * rv;
                }
            }
#pragma unroll
            for (int o = 1; o < 4; o <<= 1) {
                elA += __shfl_xor_sync(FULLMASK, elA, o);
                erA += __shfl_xor_sync(FULLMASK, erA, o);
                elB += __shfl_xor_sync(FULLMASK, elB, o);
                erB += __shfl_xor_sync(FULLMASK, erB, o);
            }
            if (t == 0) {
                int r = row0 + wm + mt * 16 + g;
                if (r < M) { el[r * NH + h] = elA; er[r * NH + h] = erA; }
                if (r + 8 < M) { el[(r + 8) * NH + h] = elB; er[(r + 8) * NH + h] = erB; }
            }
        }
    }
}

// ---------------- layer-0 aggregation: warp per dst node, 8 heads x 32 dims ----------------
__global__ void k_agg0(const float* __restrict__ b0) {
    int g = blockIdx.x * blockDim.x + threadIdx.x;
    int n = g >> 5, lane = g & 31;
    if (n >= N_NODES) return;
    int beg = g_rowptr[n], end = g_rowptr[n + 1];
    int deg = end - beg;

    float er[NH0];
#pragma unroll
    for (int h = 0; h < NH0; h++) er[h] = g_er0[n * NH0 + h];

    // pass 1: per-head max (softmax stabilization)
    float m[NH0];
#pragma unroll
    for (int h = 0; h < NH0; h++) m[h] = -INFINITY;
    for (int i = lane; i < deg; i += 32) {
        int s = g_esrc[beg + i];
        const float4* elp = (const float4*)&g_el0[s * NH0];
        float4 e0 = elp[0], e1 = elp[1];
        float ev[NH0] = {e0.x, e0.y, e0.z, e0.w, e1.x, e1.y, e1.z, e1.w};
#pragma unroll
        for (int h = 0; h < NH0; h++) {
            float e = ev[h] + er[h];
            e = (e > 0.f) ? e : 0.2f * e;
            m[h] = fmaxf(m[h], e);
        }
    }
#pragma unroll
    for (int h = 0; h < NH0; h++)
#pragma unroll
        for (int o = 16; o; o >>= 1) m[h] = fmaxf(m[h], __shfl_xor_sync(FULLMASK, m[h], o));

    // pass 2: unnormalized weighted sum + sum(exp)
    float acc[NH0], ssum[NH0];
#pragma unroll
    for (int h = 0; h < NH0; h++) { acc[h] = 0.f; ssum[h] = 0.f; }

    for (int base = 0; base < deg; base += 32) {
        int i = base + lane;
        int s = 0;
        float w[NH0];
#pragma unroll
        for (int h = 0; h < NH0; h++) w[h] = 0.f;
        if (i < deg) {
            s = g_esrc[beg + i];
            const float4* elp = (const float4*)&g_el0[s * NH0];
            float4 e0 = elp[0], e1 = elp[1];
            float ev[NH0] = {e0.x, e0.y, e0.z, e0.w, e1.x, e1.y, e1.z, e1.w};
#pragma unroll
            for (int h = 0; h < NH0; h++) {
                float e = ev[h] + er[h];
                e = (e > 0.f) ? e : 0.2f * e;
                float ww = __expf(e - m[h]);
                w[h] = ww;
                ssum[h] += ww;
            }
        }
        int cnt = deg - base; if (cnt > 32) cnt = 32;
        for (int j = 0; j < cnt; j++) {
            int sj = __shfl_sync(FULLMASK, s, j);
            const float* frow = &g_f0[sj * F0 + lane];
#pragma unroll
            for (int h = 0; h < NH0; h++) {
                float wj = __shfl_sync(FULLMASK, w[h], j);
                acc[h] += wj * frow[h * 32];
            }
        }
    }
#pragma unroll
    for (int h = 0; h < NH0; h++)
#pragma unroll
        for (int o = 16; o; o >>= 1) ssum[h] += __shfl_xor_sync(FULLMASK, ssum[h], o);

    // normalize, + bias, elu, store
#pragma unroll
    for (int h = 0; h < NH0; h++) {
        float v = (deg > 0) ? (acc[h] / ssum[h]) : 0.f;
        v += b0[h * 32 + lane];
        v = (v > 0.f) ? v : expm1f(v);
        g_h[n * F0 + h * 32 + lane] = v;
    }
}

// ---------------- layer-1 aggregation: warp per dst node, 1 head x 32 dims ----------------
__global__ void k_agg1(const float* __restrict__ b1) {
    int g = blockIdx.x * blockDim.x + threadIdx.x;
    int n = g >> 5, lane = g & 31;
    if (n >= N_NODES) return;
    int beg = g_rowptr[n], end = g_rowptr[n + 1];
    int deg = end - beg;
    float er = g_er1[n];

    float m = -INFINITY;
    for (int i = lane; i < deg; i += 32) {
        int s = g_esrc[beg + i];
        float e = g_el1[s] + er;
        e = (e > 0.f) ? e : 0.2f * e;
        m = fmaxf(m, e);
    }
#pragma unroll
    for (int o = 16; o; o >>= 1) m = fmaxf(m, __shfl_xor_sync(FULLMASK, m, o));

    float acc = 0.f, ssum = 0.f;
    for (int base = 0; base < deg; base += 32) {
        int i = base + lane;
        int s = 0;
        float w = 0.f;
        if (i < deg) {
            s = g_esrc[beg + i];
            float e = g_el1[s] + er;
            e = (e > 0.f) ? e : 0.2f * e;
            w = __expf(e - m);
            ssum += w;
        }
        int cnt = deg - base; if (cnt > 32) cnt = 32;
        for (int j = 0; j < cnt; j++) {
            int sj = __shfl_sync(FULLMASK, s, j);
            float wj = __shfl_sync(FULLMASK, w, j);
            acc += wj * g_f1[sj * F1 + lane];
        }
    }
#pragma unroll
    for (int o = 16; o; o >>= 1) ssum += __shfl_xor_sync(FULLMASK, ssum, o);

    float v = (deg > 0) ? (acc / ssum) : 0.f;
    g_h1[n * F1 + lane] = v + b1[lane];
}

// ---------------- link predictor MLP: warp per pair ----------------
__global__ void k_pred(const float* __restrict__ P1, const float* __restrict__ pb1,
                       const float* __restrict__ P2, const float* __restrict__ pb2,
                       const float* __restrict__ P3, const float* __restrict__ pb3,
                       float* __restrict__ out) {
    __shared__ float sP1[1024], sP2[1024], sP3[32], sb1[32], sb2[32];
    for (int i = threadIdx.x; i < 1024; i += blockDim.x) { sP1[i] = P1[i]; sP2[i] = P2[i]; }
    if (threadIdx.x < 32) {
        sP3[threadIdx.x] = P3[threadIdx.x];
        sb1[threadIdx.x] = pb1[threadIdx.x];
        sb2[threadIdx.x] = pb2[threadIdx.x];
    }
    __syncthreads();

    int g = blockIdx.x * blockDim.x + threadIdx.x;
    int w = g >> 5, lane = g & 31;
    if (w >= 2 * NE_PAIRS) return;
    int neg = (w >= NE_PAIRS) ? 1 : 0;
    int i = w - neg * NE_PAIRS;

    float a = g_h1[i * F1 + lane];
    int dst_row = neg ? (2 * NE_PAIRS + i) : (NE_PAIRS + i);
    float z = a * g_h1[dst_row * F1 + lane];

    // layer 1
    float y = sb1[lane];
#pragma unroll
    for (int d = 0; d < 32; d++) {
        float zd = __shfl_sync(FULLMASK, z, d);
        y += zd * sP1[d * 32 + lane];
    }
    y = fmaxf(y, 0.f);
    // layer 2
    float y2 = sb2[lane];
#pragma unroll
    for (int d = 0; d < 32; d++) {
        float yd = __shfl_sync(FULLMASK, y, d);
        y2 += yd * sP2[d * 32 + lane];
    }
    y2 = fmaxf(y2, 0.f);
    // layer 3 (32 -> 1)
    float t = y2 * sP3[lane];
#pragma unroll
    for (int o = 16; o; o >>= 1) t += __shfl_xor_sync(FULLMASK, t, o);
    if (lane == 0) out[neg * NE_PAIRS + i] = t + pb3[0];
}

// ---------------- launch ----------------
extern "C" void kernel_launch(void* const* d_in, const int* in_sizes, int n_in,
                              void* d_out, int out_size) {
    const float* x   = (const float*)d_in[0];
    const int*   src = (const int*)d_in[1];
    const int*   dst = (const int*)d_in[2];
    // d_in[3] = neg_sample_ratio (fixed = 1)
    const float* W0  = (const float*)d_in[4];
    const float* al0 = (const float*)d_in[5];
    const float* ar0 = (const float*)d_in[6];
    const float* b0  = (const float*)d_in[7];
    const float* W1  = (const float*)d_in[8];
    const float* al1 = (const float*)d_in[9];
    const float* ar1 = (const float*)d_in[10];
    const float* b1  = (const float*)d_in[11];
    const float* P1  = (const float*)d_in[12];
    const float* pb1 = (const float*)d_in[13];
    const float* P2  = (const float*)d_in[14];
    const float* pb2 = (const float*)d_in[15];
    const float* P3  = (const float*)d_in[16];
    const float* pb3 = (const float*)d_in[17];
    float* out = (float*)d_out;

    float *p_f0, *p_h, *p_f1, *p_el0, *p_er0, *p_el1, *p_er1;
    cudaGetSymbolAddress((void**)&p_f0, g_f0);
    cudaGetSymbolAddress((void**)&p_h, g_h);
    cudaGetSymbolAddress((void**)&p_f1, g_f1);
    cudaGetSymbolAddress((void**)&p_el0, g_el0);
    cudaGetSymbolAddress((void**)&p_er0, g_er0);
    cudaGetSymbolAddress((void**)&p_el1, g_el1);
    cudaGetSymbolAddress((void**)&p_er1, g_er1);

    // CSR by dst
    k_zero_cnt<<<(N_NODES + 255) / 256, 256>>>();
    k_count<<<(E_EDGES + 255) / 256, 256>>>(dst);
    k_scan<<<1, 1024>>>();
    k_zero_cnt<<<(N_NODES + 255) / 256, 256>>>();
    k_fill<<<(E_EDGES + 255) / 256, 256>>>(src, dst);

    // layer 0: tf32 GEMM + fused scores
    k_gemm_tf32<128, 64, 32, 32, 32, NH0, true>
        <<<dim3(F0 / 64, (N_NODES + 127) / 128), 256>>>(
            x, W0, p_f0, N_NODES, F0, DIN, al0, ar0, p_el0, p_er0);
    k_agg0<<<(N_NODES + 7) / 8, 256>>>(b0);

    // layer 1: tf32 GEMM + fused scores
    k_gemm_tf32<128, 32, 32, 16, 32, 1, true>
        <<<dim3(1, (N_NODES + 127) / 128), 256>>>(
            p_h, W1, p_f1, N_NODES, F1, F0, al1, ar1, p_el1, p_er1);
    k_agg1<<<(N_NODES * 32 + 255) / 256, 256>>>(b1);

    // predictor
    k_pred<<<(2 * NE_PAIRS * 32 + 255) / 256, 256>>>(P1, pb1, P2, pb2, P3, pb3, out);
}

// round 3
// speedup vs baseline: 1.6936x; 1.2292x over previous
#include <cuda_runtime.h>
#include <math.h>
#include <stdint.h>

#define N_NODES 49998
#define E_EDGES 800000
#define DIN 128
#define NH0 8
#define DOUT 32
#define F0 (NH0 * DOUT)   // 256
#define F1 32
#define NE_PAIRS (N_NODES / 3)  // 16666
#define FULLMASK 0xffffffffu

// ---------------- scratch (device globals: no runtime alloc allowed) ----------------
__device__ float g_f0[N_NODES * F0];     // layer0 projected features
__device__ float g_h[N_NODES * F0];      // elu(gat0 out)
__device__ float g_el0[N_NODES * NH0];
__device__ float g_er0[N_NODES * NH0];
__device__ float g_f1[N_NODES * F1];
__device__ float g_el1[N_NODES];
__device__ float g_er1[N_NODES];
__device__ float g_h1[N_NODES * F1];
__device__ int   g_cnt[N_NODES];
__device__ int   g_rowptr[N_NODES + 1];
__device__ int   g_cur[N_NODES];         // running cursor for fill
__device__ int   g_esrc[E_EDGES];        // src ids sorted by dst (CSR)

// ---------------- CSR build ----------------
__global__ void k_zero_cnt() {
    int i = blockIdx.x * blockDim.x + threadIdx.x;
    if (i < N_NODES) g_cnt[i] = 0;
}

__global__ void k_count(const int* __restrict__ dst) {
    int e = blockIdx.x * blockDim.x + threadIdx.x;
    if (e < E_EDGES) atomicAdd(&g_cnt[dst[e]], 1);
}

__global__ void k_scan() {
    const int T = 1024;
    int tid = threadIdx.x;
    int chunk = (N_NODES + T - 1) / T;
    int beg = tid * chunk;
    int end = beg + chunk; if (end > N_NODES) end = N_NODES;
    int s = 0;
    for (int i = beg; i < end; i++) s += g_cnt[i];
    __shared__ int sh[T];
    sh[tid] = s;
    __syncthreads();
    for (int d = 1; d < T; d <<= 1) {
        int v = (tid >= d) ? sh[tid - d] : 0;
        __syncthreads();
        sh[tid] += v;
        __syncthreads();
    }
    int run = sh[tid] - s;  // exclusive prefix
    for (int i = beg; i < end; i++) {
        g_rowptr[i] = run;
        g_cur[i] = run;      // cursor copy: fill atomics give absolute slot
        run += g_cnt[i];
    }
    if (tid == T - 1) g_rowptr[N_NODES] = sh[T - 1];
}

__global__ void k_fill(const int* __restrict__ src, const int* __restrict__ dst) {
    int e = blockIdx.x * blockDim.x + threadIdx.x;
    if (e < E_EDGES) {
        int p = atomicAdd(&g_cur[dst[e]], 1);
        g_esrc[p] = src[e];
    }
}

// ---------------- tf32 tensor-core GEMM + fused attention scores ----------------
__device__ __forceinline__ uint32_t f2tf(float f) {
    uint32_t r;
    asm("cvt.rna.tf32.f32 %0, %1;" : "=r"(r) : "f"(f));
    return r;
}

__device__ __forceinline__ void mma_tf32(float* d, const uint32_t* a, const uint32_t* b) {
    asm volatile(
        "mma.sync.aligned.m16n8k8.row.col.f32.tf32.tf32.f32 "
        "{%0,%1,%2,%3},{%4,%5,%6,%7},{%8,%9},{%0,%1,%2,%3};\n"
        : "+f"(d[0]), "+f"(d[1]), "+f"(d[2]), "+f"(d[3])
        : "r"(a[0]), "r"(a[1]), "r"(a[2]), "r"(a[3]), "r"(b[0]), "r"(b[1]));
}

// C(MxNc) = A(MxK) @ B(KxNc), tf32 inputs, fp32 accumulate.
// If SCORES: also computes el[r*NH+h] = sum_d C[r, h*32+d]*al[h*32+d] (and er).
// Requires WN == 32 (each warp owns exactly one head's columns) when SCORES.
template <int BM, int BN, int BK, int WM, int WN, int NH, bool SCORES>
__global__ void k_gemm_tf32(const float* __restrict__ A, const float* __restrict__ B,
                            float* __restrict__ C, int M, int Nc, int K,
                            const float* __restrict__ al, const float* __restrict__ ar,
                            float* __restrict__ el, float* __restrict__ er) {
    constexpr int WARPS_M = BM / WM;
    constexpr int WARPS_N = BN / WN;
    constexpr int THREADS = WARPS_M * WARPS_N * 32;
    constexpr int MT = WM / 16;
    constexpr int NT = WN / 8;
    constexpr int AP = BK + 4;
    constexpr int BP = BN + 8;

    __shared__ uint32_t As[BM][AP];
    __shared__ uint32_t Bs[BK][BP];

    const int tid = threadIdx.x;
    const int wid = tid >> 5, lane = tid & 31;
    const int wm = (wid / WARPS_N) * WM;
    const int wn = (wid % WARPS_N) * WN;
    const int g = lane >> 2, t = lane & 3;
    const int row0 = blockIdx.y * BM, col0 = blockIdx.x * BN;

    float acc[MT][NT][4];
#pragma unroll
    for (int mt = 0; mt < MT; mt++)
#pragma unroll
        for (int nt = 0; nt < NT; nt++)
#pragma unroll
            for (int j = 0; j < 4; j++) acc[mt][nt][j] = 0.f;

    constexpr int A_CG = BK / 4;
    constexpr int A_RPP = THREADS / A_CG;
    constexpr int NB4 = BN / 4;
    constexpr int B_RPP = THREADS / NB4;

    for (int k0 = 0; k0 < K; k0 += BK) {
#pragma unroll
        for (int i = 0; i < BM / A_RPP; i++) {
            int r = (tid / A_CG) + i * A_RPP;
            int c = (tid % A_CG) * 4;
            int gr = row0 + r;
            float4 v = make_float4(0.f, 0.f, 0.f, 0.f);
            if (gr < M) v = *(const float4*)&A[(long)gr * K + k0 + c];
            As[r][c + 0] = f2tf(v.x);
            As[r][c + 1] = f2tf(v.y);
            As[r][c + 2] = f2tf(v.z);
            As[r][c + 3] = f2tf(v.w);
        }
#pragma unroll
        for (int i = 0; i < BK / B_RPP; i++) {
            int r = tid / NB4 + i * B_RPP;
            int c = (tid % NB4) * 4;
            float4 v = *(const float4*)&B[(long)(k0 + r) * Nc + col0 + c];
            Bs[r][c + 0] = f2tf(v.x);
            Bs[r][c + 1] = f2tf(v.y);
            Bs[r][c + 2] = f2tf(v.z);
            Bs[r][c + 3] = f2tf(v.w);
        }
        __syncthreads();

#pragma unroll
        for (int ks = 0; ks < BK / 8; ks++) {
            const int k8 = ks * 8;
            uint32_t af[MT][4], bf[NT][2];
#pragma unroll
            for (int mt = 0; mt < MT; mt++) {
                int r = wm + mt * 16;
                af[mt][0] = As[r + g][k8 + t];
                af[mt][1] = As[r + g + 8][k8 + t];
                af[mt][2] = As[r + g][k8 + t + 4];
                af[mt][3] = As[r + g + 8][k8 + t + 4];
            }
#pragma unroll
            for (int nt = 0; nt < NT; nt++) {
                int c = wn + nt * 8 + g;
                bf[nt][0] = Bs[k8 + t][c];
                bf[nt][1] = Bs[k8 + t + 4][c];
            }
#pragma unroll
            for (int mt = 0; mt < MT; mt++)
#pragma unroll
                for (int nt = 0; nt < NT; nt++) mma_tf32(acc[mt][nt], af[mt], bf[nt]);
        }
        __syncthreads();
    }

#pragma unroll
    for (int mt = 0; mt < MT; mt++) {
#pragma unroll
        for (int nt = 0; nt < NT; nt++) {
            int mr = row0 + wm + mt * 16 + g;
            int c = col0 + wn + nt * 8 + 2 * t;
            if (mr < M)
                *(float2*)&C[(long)mr * Nc + c] = make_float2(acc[mt][nt][0], acc[mt][nt][1]);
            if (mr + 8 < M)
                *(float2*)&C[(long)(mr + 8) * Nc + c] = make_float2(acc[mt][nt][2], acc[mt][nt][3]);
        }
    }

    if (SCORES) {
        const int h = (col0 + wn) >> 5;
#pragma unroll
        for (int mt = 0; mt < MT; mt++) {
            float elA = 0.f, erA = 0.f;
            float elB = 0.f, erB = 0.f;
#pragma unroll
            for (int nt = 0; nt < NT; nt++) {
#pragma unroll
                for (int j = 0; j < 2; j++) {
                    int c = nt * 8 + 2 * t + j;
                    float av = al[h * 32 + c];
                    float rv = ar[h * 32 + c];
                    elA += acc[mt][nt][j] * av;
                    erA += acc[mt][nt][j] * rv;
                    elB += acc[mt][nt][2 + j] * av;
                    erB += acc[mt][nt][2 + j] * rv;
                }
            }
#pragma unroll
            for (int o = 1; o < 4; o <<= 1) {
                elA += __shfl_xor_sync(FULLMASK, elA, o);
                erA += __shfl_xor_sync(FULLMASK, erA, o);
                elB += __shfl_xor_sync(FULLMASK, elB, o);
                erB += __shfl_xor_sync(FULLMASK, erB, o);
            }
            if (t == 0) {
                int r = row0 + wm + mt * 16 + g;
                if (r < M) { el[r * NH + h] = elA; er[r * NH + h] = erA; }
                if (r + 8 < M) { el[(r + 8) * NH + h] = elB; er[(r + 8) * NH + h] = erB; }
            }
        }
    }
}

// ---------------- layer-0 aggregation (single pass, no max) ----------------
// warp per dst node; lane l owns dims [l*8, l*8+8) — all within head l/4.
// Per edge: 1 shfl(src) + 1 smem weight read + 2 LDG.128 + 8 FFMA.
__global__ void k_agg0(const float* __restrict__ b0) {
    __shared__ float swW[8][32 * 9];  // [warp][edge*9 + head], pad 9 -> conflict-free
    __shared__ float swS[8][8];       // per-head weight sums

    int gt = blockIdx.x * blockDim.x + threadIdx.x;
    int n = gt >> 5, lane = gt & 31;
    int warp = threadIdx.x >> 5;
    if (n >= N_NODES) return;
    int beg = g_rowptr[n], end = g_rowptr[n + 1];
    int deg = end - beg;
    const int hsel = lane >> 2;

    // er for this dst (same for all lanes)
    float er[NH0];
    {
        const float4* erp = (const float4*)&g_er0[n * NH0];
        float4 e0 = erp[0], e1 = erp[1];
        er[0] = e0.x; er[1] = e0.y; er[2] = e0.z; er[3] = e0.w;
        er[4] = e1.x; er[5] = e1.y; er[6] = e1.z; er[7] = e1.w;
    }

    float4 acc0 = make_float4(0.f, 0.f, 0.f, 0.f);
    float4 acc1 = make_float4(0.f, 0.f, 0.f, 0.f);
    float ssum[NH0];
#pragma unroll
    for (int h = 0; h < NH0; h++) ssum[h] = 0.f;

    for (int base = 0; base < deg; base += 32) {
        int i = base + lane;
        int s = 0;
        float w[NH0];
#pragma unroll
        for (int h = 0; h < NH0; h++) w[h] = 0.f;
        if (i < deg) {
            s = g_esrc[beg + i];
            const float4* elp = (const float4*)&g_el0[s * NH0];
            float4 e0 = elp[0], e1 = elp[1];
            float ev[NH0] = {e0.x, e0.y, e0.z, e0.w, e1.x, e1.y, e1.z, e1.w};
#pragma unroll
            for (int h = 0; h < NH0; h++) {
                float e = ev[h] + er[h];
                e = (e > 0.f) ? e : 0.2f * e;     // leaky relu
                float ww = __expf(e);              // scores bounded -> no max needed
                w[h] = ww;
                ssum[h] += ww;
            }
        }
#pragma unroll
        for (int h = 0; h < NH0; h++) swW[warp][lane * 9 + h] = w[h];
        __syncwarp();

        int cnt = deg - base; if (cnt > 32) cnt = 32;
        for (int j = 0; j < cnt; j++) {
            int sj = __shfl_sync(FULLMASK, s, j);
            float wj = swW[warp][j * 9 + hsel];
            const float4* fp = (const float4*)&g_f0[sj * F0 + lane * 8];
            float4 fa = fp[0], fb = fp[1];
            acc0.x += wj * fa.x; acc0.y += wj * fa.y;
            acc0.z += wj * fa.z; acc0.w += wj * fa.w;
            acc1.x += wj * fb.x; acc1.y += wj * fb.y;
            acc1.z += wj * fb.z; acc1.w += wj * fb.w;
        }
        __syncwarp();
    }

    // warp-reduce per-head weight sums; lane h publishes head h's total
#pragma unroll
    for (int h = 0; h < NH0; h++) {
        float r = ssum[h];
#pragma unroll
        for (int o = 16; o; o >>= 1) r += __shfl_xor_sync(FULLMASK, r, o);
        if (lane == h) swS[warp][h] = r;
    }
    __syncwarp();
    float inv = (deg > 0) ? (1.f / swS[warp][hsel]) : 0.f;

    // normalize + bias + elu + store (lane's 8 contiguous dims)
    const float4* bp = (const float4*)&b0[lane * 8];
    float4 b_lo = bp[0], b_hi = bp[1];
    float v[8] = {acc0.x, acc0.y, acc0.z, acc0.w, acc1.x, acc1.y, acc1.z, acc1.w};
    float bb[8] = {b_lo.x, b_lo.y, b_lo.z, b_lo.w, b_hi.x, b_hi.y, b_hi.z, b_hi.w};
#pragma unroll
    for (int k = 0; k < 8; k++) {
        float t = v[k] * inv + bb[k];
        v[k] = (t > 0.f) ? t : expm1f(t);
    }
    float4* op = (float4*)&g_h[n * F0 + lane * 8];
    op[0] = make_float4(v[0], v[1], v[2], v[3]);
    op[1] = make_float4(v[4], v[5], v[6], v[7]);
}

// ---------------- layer-1 aggregation (single pass, no max) ----------------
__global__ void k_agg1(const float* __restrict__ b1) {
    int g = blockIdx.x * blockDim.x + threadIdx.x;
    int n = g >> 5, lane = g & 31;
    if (n >= N_NODES) return;
    int beg = g_rowptr[n], end = g_rowptr[n + 1];
    int deg = end - beg;
    float er = g_er1[n];

    float acc = 0.f, ssum = 0.f;
    for (int base = 0; base < deg; base += 32) {
        int i = base + lane;
        int s = 0;
        float w = 0.f;
        if (i < deg) {
            s = g_esrc[beg + i];
            float e = g_el1[s] + er;
            e = (e > 0.f) ? e : 0.2f * e;
            w = __expf(e);
            ssum += w;
        }
        int cnt = deg - base; if (cnt > 32) cnt = 32;
        for (int j = 0; j < cnt; j++) {
            int sj = __shfl_sync(FULLMASK, s, j);
            float wj = __shfl_sync(FULLMASK, w, j);
            acc += wj * g_f1[sj * F1 + lane];
        }
    }
#pragma unroll
    for (int o = 16; o; o >>= 1) ssum += __shfl_xor_sync(FULLMASK, ssum, o);

    float v = (deg > 0) ? (acc / ssum) : 0.f;
    g_h1[n * F1 + lane] = v + b1[lane];
}

// ---------------- link predictor MLP: warp per pair ----------------
__global__ void k_pred(const float* __restrict__ P1, const float* __restrict__ pb1,
                       const float* __restrict__ P2, const float* __restrict__ pb2,
                       const float* __restrict__ P3, const float* __restrict__ pb3,
                       float* __restrict__ out) {
    __shared__ float sP1[1024], sP2[1024], sP3[32], sb1[32], sb2[32];
    for (int i = threadIdx.x; i < 1024; i += blockDim.x) { sP1[i] = P1[i]; sP2[i] = P2[i]; }
    if (threadIdx.x < 32) {
        sP3[threadIdx.x] = P3[threadIdx.x];
        sb1[threadIdx.x] = pb1[threadIdx.x];
        sb2[threadIdx.x] = pb2[threadIdx.x];
    }
    __syncthreads();

    int g = blockIdx.x * blockDim.x + threadIdx.x;
    int w = g >> 5, lane = g & 31;
    if (w >= 2 * NE_PAIRS) return;
    int neg = (w >= NE_PAIRS) ? 1 : 0;
    int i = w - neg * NE_PAIRS;

    float a = g_h1[i * F1 + lane];
    int dst_row = neg ? (2 * NE_PAIRS + i) : (NE_PAIRS + i);
    float z = a * g_h1[dst_row * F1 + lane];

    float y = sb1[lane];
#pragma unroll
    for (int d = 0; d < 32; d++) {
        float zd = __shfl_sync(FULLMASK, z, d);
        y += zd * sP1[d * 32 + lane];
    }
    y = fmaxf(y, 0.f);
    float y2 = sb2[lane];
#pragma unroll
    for (int d = 0; d < 32; d++) {
        float yd = __shfl_sync(FULLMASK, y, d);
        y2 += yd * sP2[d * 32 + lane];
    }
    y2 = fmaxf(y2, 0.f);
    float t = y2 * sP3[lane];
#pragma unroll
    for (int o = 16; o; o >>= 1) t += __shfl_xor_sync(FULLMASK, t, o);
    if (lane == 0) out[neg * NE_PAIRS + i] = t + pb3[0];
}

// ---------------- launch ----------------
extern "C" void kernel_launch(void* const* d_in, const int* in_sizes, int n_in,
                              void* d_out, int out_size) {
    const float* x   = (const float*)d_in[0];
    const int*   src = (const int*)d_in[1];
    const int*   dst = (const int*)d_in[2];
    const float* W0  = (const float*)d_in[4];
    const float* al0 = (const float*)d_in[5];
    const float* ar0 = (const float*)d_in[6];
    const float* b0  = (const float*)d_in[7];
    const float* W1  = (const float*)d_in[8];
    const float* al1 = (const float*)d_in[9];
    const float* ar1 = (const float*)d_in[10];
    const float* b1  = (const float*)d_in[11];
    const float* P1  = (const float*)d_in[12];
    const float* pb1 = (const float*)d_in[13];
    const float* P2  = (const float*)d_in[14];
    const float* pb2 = (const float*)d_in[15];
    const float* P3  = (const float*)d_in[16];
    const float* pb3 = (const float*)d_in[17];
    float* out = (float*)d_out;

    float *p_f0, *p_h, *p_f1, *p_el0, *p_er0, *p_el1, *p_er1;
    cudaGetSymbolAddress((void**)&p_f0, g_f0);
    cudaGetSymbolAddress((void**)&p_h, g_h);
    cudaGetSymbolAddress((void**)&p_f1, g_f1);
    cudaGetSymbolAddress((void**)&p_el0, g_el0);
    cudaGetSymbolAddress((void**)&p_er0, g_er0);
    cudaGetSymbolAddress((void**)&p_el1, g_el1);
    cudaGetSymbolAddress((void**)&p_er1, g_er1);

    // CSR by dst (scan emits rowptr + cursor copy; fill atomics are absolute)
    k_zero_cnt<<<(N_NODES + 255) / 256, 256>>>();
    k_count<<<(E_EDGES + 255) / 256, 256>>>(dst);
    k_scan<<<1, 1024>>>();
    k_fill<<<(E_EDGES + 255) / 256, 256>>>(src, dst);

    // layer 0: tf32 GEMM + fused scores
    k_gemm_tf32<128, 64, 32, 32, 32, NH0, true>
        <<<dim3(F0 / 64, (N_NODES + 127) / 128), 256>>>(
            x, W0, p_f0, N_NODES, F0, DIN, al0, ar0, p_el0, p_er0);
    k_agg0<<<(N_NODES + 7) / 8, 256>>>(b0);

    // layer 1: tf32 GEMM + fused scores
    k_gemm_tf32<128, 32, 32, 16, 32, 1, true>
        <<<dim3(1, (N_NODES + 127) / 128), 256>>>(
            p_h, W1, p_f1, N_NODES, F1, F0, al1, ar1, p_el1, p_er1);
    k_agg1<<<(N_NODES * 32 + 255) / 256, 256>>>(b1);

    // predictor
    k_pred<<<(2 * NE_PAIRS * 32 + 255) / 256, 256>>>(P1, pb1, P2, pb2, P3, pb3, out);
}

// round 8
// speedup vs baseline: 1.8256x; 1.0779x over previous
#include <cuda_runtime.h>
#include <cuda_fp16.h>
#include <math.h>
#include <stdint.h>

#define N_NODES 49998
#define E_EDGES 800000
#define DIN 128
#define NH0 8
#define DOUT 32
#define F0 (NH0 * DOUT)   // 256
#define F1 32
#define NE_PAIRS (N_NODES / 3)  // 16666
#define FULLMASK 0xffffffffu

// ---------------- scratch (device globals: no runtime alloc allowed) ----------------
__device__ __half g_f0h[N_NODES * F0];   // layer0 projected features (fp16 payload)
__device__ float g_h[N_NODES * F0];      // elu(gat0 out)
__device__ float g_el0[N_NODES * NH0];
__device__ float g_er0[N_NODES * NH0];
__device__ float g_f1[N_NODES * F1];
__device__ float g_el1[N_NODES];
__device__ float g_er1[N_NODES];
__device__ float g_h1[N_NODES * F1];
__device__ int   g_cnt[N_NODES];
__device__ int   g_rowptr[N_NODES + 1];
__device__ int   g_cur[N_NODES];
__device__ int   g_esrc[E_EDGES];

// ---------------- CSR build ----------------
__global__ void k_zero_cnt() {
    int i = blockIdx.x * blockDim.x + threadIdx.x;
    if (i < N_NODES) g_cnt[i] = 0;
}

__global__ void k_count(const int* __restrict__ dst) {
    int e = blockIdx.x * blockDim.x + threadIdx.x;
    if (e < E_EDGES) atomicAdd(&g_cnt[dst[e]], 1);
}

__global__ void k_scan() {
    const int T = 1024;
    int tid = threadIdx.x;
    int chunk = (N_NODES + T - 1) / T;
    int beg = tid * chunk;
    int end = beg + chunk; if (end > N_NODES) end = N_NODES;
    int s = 0;
    for (int i = beg; i < end; i++) s += g_cnt[i];
    __shared__ int sh[T];
    sh[tid] = s;
    __syncthreads();
    for (int d = 1; d < T; d <<= 1) {
        int v = (tid >= d) ? sh[tid - d] : 0;
        __syncthreads();
        sh[tid] += v;
        __syncthreads();
    }
    int run = sh[tid] - s;
    for (int i = beg; i < end; i++) {
        g_rowptr[i] = run;
        g_cur[i] = run;
        run += g_cnt[i];
    }
    if (tid == T - 1) g_rowptr[N_NODES] = sh[T - 1];
}

__global__ void k_fill(const int* __restrict__ src, const int* __restrict__ dst) {
    int e = blockIdx.x * blockDim.x + threadIdx.x;
    if (e < E_EDGES) {
        int p = atomicAdd(&g_cur[dst[e]], 1);
        g_esrc[p] = src[e];
    }
}

// ---------------- tf32 tensor-core GEMM + fused attention scores ----------------
__device__ __forceinline__ uint32_t f2tf(float f) {
    uint32_t r;
    asm("cvt.rna.tf32.f32 %0, %1;" : "=r"(r) : "f"(f));
    return r;
}

__device__ __forceinline__ void mma_tf32(float* d, const uint32_t* a, const uint32_t* b) {
    asm volatile(
        "mma.sync.aligned.m16n8k8.row.col.f32.tf32.tf32.f32 "
        "{%0,%1,%2,%3},{%4,%5,%6,%7},{%8,%9},{%0,%1,%2,%3};\n"
        : "+f"(d[0]), "+f"(d[1]), "+f"(d[2]), "+f"(d[3])
        : "r"(a[0]), "r"(a[1]), "r"(a[2]), "r"(a[3]), "r"(b[0]), "r"(b[1]));
}

// C(MxNc) = A(MxK) @ B(KxNc), tf32 inputs, fp32 accumulate.
// HALF_OUT: C stored as __half. SCORES: fused el/er epilogue (needs WN==32).
template <int BM, int BN, int BK, int WM, int WN, int NH, bool SCORES, bool HALF_OUT>
__global__ void k_gemm_tf32(const float* __restrict__ A, const float* __restrict__ B,
                            void* __restrict__ Cv, int M, int Nc, int K,
                            const float* __restrict__ al, const float* __restrict__ ar,
                            float* __restrict__ el, float* __restrict__ er) {
    constexpr int WARPS_M = BM / WM;
    constexpr int WARPS_N = BN / WN;
    constexpr int THREADS = WARPS_M * WARPS_N * 32;
    constexpr int MT = WM / 16;
    constexpr int NT = WN / 8;
    constexpr int AP = BK + 4;
    constexpr int BP = BN + 8;

    __shared__ uint32_t As[BM][AP];
    __shared__ uint32_t Bs[BK][BP];

    const int tid = threadIdx.x;
    const int wid = tid >> 5, lane = tid & 31;
    const int wm = (wid / WARPS_N) * WM;
    const int wn = (wid % WARPS_N) * WN;
    const int g = lane >> 2, t = lane & 3;
    const int row0 = blockIdx.y * BM, col0 = blockIdx.x * BN;

    float acc[MT][NT][4];
#pragma unroll
    for (int mt = 0; mt < MT; mt++)
#pragma unroll
        for (int nt = 0; nt < NT; nt++)
#pragma unroll
            for (int j = 0; j < 4; j++) acc[mt][nt][j] = 0.f;

    constexpr int A_CG = BK / 4;
    constexpr int A_RPP = THREADS / A_CG;
    constexpr int NB4 = BN / 4;
    constexpr int B_RPP = THREADS / NB4;

    for (int k0 = 0; k0 < K; k0 += BK) {
#pragma unroll
        for (int i = 0; i < BM / A_RPP; i++) {
            int r = (tid / A_CG) + i * A_RPP;
            int c = (tid % A_CG) * 4;
            int gr = row0 + r;
            float4 v = make_float4(0.f, 0.f, 0.f, 0.f);
            if (gr < M) v = *(const float4*)&A[(long)gr * K + k0 + c];
            As[r][c + 0] = f2tf(v.x);
            As[r][c + 1] = f2tf(v.y);
            As[r][c + 2] = f2tf(v.z);
            As[r][c + 3] = f2tf(v.w);
        }
#pragma unroll
        for (int i = 0; i < BK / B_RPP; i++) {
            int r = tid / NB4 + i * B_RPP;
            int c = (tid % NB4) * 4;
            float4 v = *(const float4*)&B[(long)(k0 + r) * Nc + col0 + c];
            Bs[r][c + 0] = f2tf(v.x);
            Bs[r][c + 1] = f2tf(v.y);
            Bs[r][c + 2] = f2tf(v.z);
            Bs[r][c + 3] = f2tf(v.w);
        }
        __syncthreads();

#pragma unroll
        for (int ks = 0; ks < BK / 8; ks++) {
            const int k8 = ks * 8;
            uint32_t af[MT][4], bf[NT][2];
#pragma unroll
            for (int mt = 0; mt < MT; mt++) {
                int r = wm + mt * 16;
                af[mt][0] = As[r + g][k8 + t];
                af[mt][1] = As[r + g + 8][k8 + t];
                af[mt][2] = As[r + g][k8 + t + 4];
                af[mt][3] = As[r + g + 8][k8 + t + 4];
            }
#pragma unroll
            for (int nt = 0; nt < NT; nt++) {
                int c = wn + nt * 8 + g;
                bf[nt][0] = Bs[k8 + t][c];
                bf[nt][1] = Bs[k8 + t + 4][c];
            }
#pragma unroll
            for (int mt = 0; mt < MT; mt++)
#pragma unroll
                for (int nt = 0; nt < NT; nt++) mma_tf32(acc[mt][nt], af[mt], bf[nt]);
        }
        __syncthreads();
    }

#pragma unroll
    for (int mt = 0; mt < MT; mt++) {
#pragma unroll
        for (int nt = 0; nt < NT; nt++) {
            int mr = row0 + wm + mt * 16 + g;
            int c = col0 + wn + nt * 8 + 2 * t;
            if (HALF_OUT) {
                __half* C = (__half*)Cv;
                if (mr < M)
                    *(__half2*)&C[(long)mr * Nc + c] = __floats2half2_rn(acc[mt][nt][0], acc[mt][nt][1]);
                if (mr + 8 < M)
                    *(__half2*)&C[(long)(mr + 8) * Nc + c] = __floats2half2_rn(acc[mt][nt][2], acc[mt][nt][3]);
            } else {
                float* C = (float*)Cv;
                if (mr < M)
                    *(float2*)&C[(long)mr * Nc + c] = make_float2(acc[mt][nt][0], acc[mt][nt][1]);
                if (mr + 8 < M)
                    *(float2*)&C[(long)(mr + 8) * Nc + c] = make_float2(acc[mt][nt][2], acc[mt][nt][3]);
            }
        }
    }

    if (SCORES) {
        const int h = (col0 + wn) >> 5;
#pragma unroll
        for (int mt = 0; mt < MT; mt++) {
            float elA = 0.f, erA = 0.f;
            float elB = 0.f, erB = 0.f;
#pragma unroll
            for (int nt = 0; nt < NT; nt++) {
#pragma unroll
                for (int j = 0; j < 2; j++) {
                    int c = nt * 8 + 2 * t + j;
                    float av = al[h * 32 + c];
                    float rv = ar[h * 32 + c];
                    elA += acc[mt][nt][j] * av;
                    erA += acc[mt][nt][j] * rv;
                    elB += acc[mt][nt][2 + j] * av;
                    erB += acc[mt][nt][2 + j] * rv;
                }
            }
#pragma unroll
            for (int o = 1; o < 4; o <<= 1) {
                elA += __shfl_xor_sync(FULLMASK, elA, o);
                erA += __shfl_xor_sync(FULLMASK, erA, o);
                elB += __shfl_xor_sync(FULLMASK, elB, o);
                erB += __shfl_xor_sync(FULLMASK, erB, o);
            }
            if (t == 0) {
                int r = row0 + wm + mt * 16 + g;
                if (r < M) { el[r * NH + h] = elA; er[r * NH + h] = erA; }
                if (r + 8 < M) { el[(r + 8) * NH + h] = elB; er[(r + 8) * NH + h] = erB; }
            }
        }
    }
}

// ---------------- layer-0 aggregation (single pass, fp16 gather) ----------------
// warp per dst node; lane l owns dims [l*8, l*8+8) — all within head l/4.
// Per edge: 1 shfl(src) + 1 smem weight read + 1 LDG.128 (8 halves) + 8 FFMA.
__global__ void k_agg0(const float* __restrict__ b0) {
    __shared__ float swW[8][32 * 9];
    __shared__ float swS[8][8];

    int gt = blockIdx.x * blockDim.x + threadIdx.x;
    int n = gt >> 5, lane = gt & 31;
    int warp = threadIdx.x >> 5;
    if (n >= N_NODES) return;
    int beg = g_rowptr[n], end = g_rowptr[n + 1];
    int deg = end - beg;
    const int hsel = lane >> 2;

    float er[NH0];
    {
        const float4* erp = (const float4*)&g_er0[n * NH0];
        float4 e0 = erp[0], e1 = erp[1];
        er[0] = e0.x; er[1] = e0.y; er[2] = e0.z; er[3] = e0.w;
        er[4] = e1.x; er[5] = e1.y; er[6] = e1.z; er[7] = e1.w;
    }

    float acc[8];
#pragma unroll
    for (int k = 0; k < 8; k++) acc[k] = 0.f;
    float ssum[NH0];
#pragma unroll
    for (int h = 0; h < NH0; h++) ssum[h] = 0.f;

    for (int base = 0; base < deg; base += 32) {
        int i = base + lane;
        int s = 0;
        float w[NH0];
#pragma unroll
        for (int h = 0; h < NH0; h++) w[h] = 0.f;
        if (i < deg) {
            s = g_esrc[beg + i];
            const float4* elp = (const float4*)&g_el0[s * NH0];
            float4 e0 = elp[0], e1 = elp[1];
            float ev[NH0] = {e0.x, e0.y, e0.z, e0.w, e1.x, e1.y, e1.z, e1.w};
#pragma unroll
            for (int h = 0; h < NH0; h++) {
                float e = ev[h] + er[h];
                e = (e > 0.f) ? e : 0.2f * e;
                float ww = __expf(e);
                w[h] = ww;
                ssum[h] += ww;
            }
        }
#pragma unroll
        for (int h = 0; h < NH0; h++) swW[warp][lane * 9 + h] = w[h];
        __syncwarp();

        int cnt = deg - base; if (cnt > 32) cnt = 32;
        for (int j = 0; j < cnt; j++) {
            int sj = __shfl_sync(FULLMASK, s, j);
            float wj = swW[warp][j * 9 + hsel];
            uint4 raw = *(const uint4*)&g_f0h[sj * F0 + lane * 8];
            float2 p0 = __half22float2(*(__half2*)&raw.x);
            float2 p1 = __half22float2(*(__half2*)&raw.y);
            float2 p2 = __half22float2(*(__half2*)&raw.z);
            float2 p3 = __half22float2(*(__half2*)&raw.w);
            acc[0] += wj * p0.x; acc[1] += wj * p0.y;
            acc[2] += wj * p1.x; acc[3] += wj * p1.y;
            acc[4] += wj * p2.x; acc[5] += wj * p2.y;
            acc[6] += wj * p3.x; acc[7] += wj * p3.y;
        }
        __syncwarp();
    }

#pragma unroll
    for (int h = 0; h < NH0; h++) {
        float r = ssum[h];
#pragma unroll
        for (int o = 16; o; o >>= 1) r += __shfl_xor_sync(FULLMASK, r, o);
        if (lane == h) swS[warp][h] = r;
    }
    __syncwarp();
    float inv = (deg > 0) ? (1.f / swS[warp][hsel]) : 0.f;

    const float4* bp = (const float4*)&b0[lane * 8];
    float4 b_lo = bp[0], b_hi = bp[1];
    float bb[8] = {b_lo.x, b_lo.y, b_lo.z, b_lo.w, b_hi.x, b_hi.y, b_hi.z, b_hi.w};
    float v[8];
#pragma unroll
    for (int k = 0; k < 8; k++) {
        float t = acc[k] * inv + bb[k];
        v[k] = (t > 0.f) ? t : expm1f(t);
    }
    float4* op = (float4*)&g_h[n * F0 + lane * 8];
    op[0] = make_float4(v[0], v[1], v[2], v[3]);
    op[1] = make_float4(v[4], v[5], v[6], v[7]);
}

// ---------------- layer-1 aggregation (single pass, no max) ----------------
__global__ void k_agg1(const float* __restrict__ b1) {
    int g = blockIdx.x * blockDim.x + threadIdx.x;
    int n = g >> 5, lane = g & 31;
    if (n >= N_NODES) return;
    int beg = g_rowptr[n], end = g_rowptr[n + 1];
    int deg = end - beg;
    float er = g_er1[n];

    float acc = 0.f, ssum = 0.f;
    for (int base = 0; base < deg; base += 32) {
        int i = base + lane;
        int s = 0;
        float w = 0.f;
        if (i < deg) {
            s = g_esrc[beg + i];
            float e = g_el1[s] + er;
            e = (e > 0.f) ? e : 0.2f * e;
            w = __expf(e);
            ssum += w;
        }
        int cnt = deg - base; if (cnt > 32) cnt = 32;
        for (int j = 0; j < cnt; j++) {
            int sj = __shfl_sync(FULLMASK, s, j);
            float wj = __shfl_sync(FULLMASK, w, j);
            acc += wj * g_f1[sj * F1 + lane];
        }
    }
#pragma unroll
    for (int o = 16; o; o >>= 1) ssum += __shfl_xor_sync(FULLMASK, ssum, o);

    float v = (deg > 0) ? (acc / ssum) : 0.f;
    g_h1[n * F1 + lane] = v + b1[lane];
}

// ---------------- link predictor MLP: warp per pair ----------------
__global__ void k_pred(const float* __restrict__ P1, const float* __restrict__ pb1,
                       const float* __restrict__ P2, const float* __restrict__ pb2,
                       const float* __restrict__ P3, const float* __restrict__ pb3,
                       float* __restrict__ out) {
    __shared__ float sP1[1024], sP2[1024], sP3[32], sb1[32], sb2[32];
    for (int i = threadIdx.x; i < 1024; i += blockDim.x) { sP1[i] = P1[i]; sP2[i] = P2[i]; }
    if (threadIdx.x < 32) {
        sP3[threadIdx.x] = P3[threadIdx.x];
        sb1[threadIdx.x] = pb1[threadIdx.x];
        sb2[threadIdx.x] = pb2[threadIdx.x];
    }
    __syncthreads();

    int g = blockIdx.x * blockDim.x + threadIdx.x;
    int w = g >> 5, lane = g & 31;
    if (w >= 2 * NE_PAIRS) return;
    int neg = (w >= NE_PAIRS) ? 1 : 0;
    int i = w - neg * NE_PAIRS;

    float a = g_h1[i * F1 + lane];
    int dst_row = neg ? (2 * NE_PAIRS + i) : (NE_PAIRS + i);
    float z = a * g_h1[dst_row * F1 + lane];

    float y = sb1[lane];
#pragma unroll
    for (int d = 0; d < 32; d++) {
        float zd = __shfl_sync(FULLMASK, z, d);
        y += zd * sP1[d * 32 + lane];
    }
    y = fmaxf(y, 0.f);
    float y2 = sb2[lane];
#pragma unroll
    for (int d = 0; d < 32; d++) {
        float yd = __shfl_sync(FULLMASK, y, d);
        y2 += yd * sP2[d * 32 + lane];
    }
    y2 = fmaxf(y2, 0.f);
    float t = y2 * sP3[lane];
#pragma unroll
    for (int o = 16; o; o >>= 1) t += __shfl_xor_sync(FULLMASK, t, o);
    if (lane == 0) out[neg * NE_PAIRS + i] = t + pb3[0];
}

// ---------------- launch ----------------
extern "C" void kernel_launch(void* const* d_in, const int* in_sizes, int n_in,
                              void* d_out, int out_size) {
    const float* x   = (const float*)d_in[0];
    const int*   src = (const int*)d_in[1];
    const int*   dst = (const int*)d_in[2];
    const float* W0  = (const float*)d_in[4];
    const float* al0 = (const float*)d_in[5];
    const float* ar0 = (const float*)d_in[6];
    const float* b0  = (const float*)d_in[7];
    const float* W1  = (const float*)d_in[8];
    const float* al1 = (const float*)d_in[9];
    const float* ar1 = (const float*)d_in[10];
    const float* b1  = (const float*)d_in[11];
    const float* P1  = (const float*)d_in[12];
    const float* pb1 = (const float*)d_in[13];
    const float* P2  = (const float*)d_in[14];
    const float* pb2 = (const float*)d_in[15];
    const float* P3  = (const float*)d_in[16];
    const float* pb3 = (const float*)d_in[17];
    float* out = (float*)d_out;

    void *p_f0h;
    float *p_h, *p_f1, *p_el0, *p_er0, *p_el1, *p_er1;
    cudaGetSymbolAddress(&p_f0h, g_f0h);
    cudaGetSymbolAddress((void**)&p_h, g_h);
    cudaGetSymbolAddress((void**)&p_f1, g_f1);
    cudaGetSymbolAddress((void**)&p_el0, g_el0);
    cudaGetSymbolAddress((void**)&p_er0, g_er0);
    cudaGetSymbolAddress((void**)&p_el1, g_el1);
    cudaGetSymbolAddress((void**)&p_er1, g_er1);

    // second stream for CSR build, overlapped with GEMM0 (event fork/join
    // keeps everything inside the captured graph)
    static cudaStream_t sB = nullptr;
    static cudaEvent_t evFork = nullptr, evJoin = nullptr;
    if (sB == nullptr) {
        cudaStreamCreateWithFlags(&sB, cudaStreamNonBlocking);
        cudaEventCreateWithFlags(&evFork, cudaEventDisableTiming);
        cudaEventCreateWithFlags(&evJoin, cudaEventDisableTiming);
    }

    cudaEventRecord(evFork, 0);
    cudaStreamWaitEvent(sB, evFork, 0);

    // branch B: CSR by dst
    k_zero_cnt<<<(N_NODES + 255) / 256, 256, 0, sB>>>();
    k_count<<<(E_EDGES + 255) / 256, 256, 0, sB>>>(dst);
    k_scan<<<1, 1024, 0, sB>>>();
    k_fill<<<(E_EDGES + 255) / 256, 256, 0, sB>>>(src, dst);
    cudaEventRecord(evJoin, sB);

    // branch A (default stream): layer-0 GEMM (tf32) + fused scores, fp16 out
    k_gemm_tf32<128, 64, 32, 32, 32, NH0, true, true>
        <<<dim3(F0 / 64, (N_NODES + 127) / 128), 256>>>(
            x, W0, p_f0h, N_NODES, F0, DIN, al0, ar0, p_el0, p_er0);

    cudaStreamWaitEvent(0, evJoin, 0);

    k_agg0<<<(N_NODES + 7) / 8, 256>>>(b0);

    // layer 1: tf32 GEMM + fused scores (fp32 out)
    k_gemm_tf32<128, 32, 32, 16, 32, 1, true, false>
        <<<dim3(1, (N_NODES + 127) / 128), 256>>>(
            p_h, W1, p_f1, N_NODES, F1, F0, al1, ar1, p_el1, p_er1);
    k_agg1<<<(N_NODES * 32 + 255) / 256, 256>>>(b1);

    // predictor
    k_pred<<<(2 * NE_PAIRS * 32 + 255) / 256, 256>>>(P1, pb1, P2, pb2, P3, pb3, out);
}

// round 10
// speedup vs baseline: 1.8645x; 1.0213x over previous
#include <cuda_runtime.h>
#include <cuda_fp16.h>
#include <math.h>
#include <stdint.h>

#define N_NODES 49998
#define E_EDGES 800000
#define DIN 128
#define NH0 8
#define DOUT 32
#define F0 (NH0 * DOUT)   // 256
#define F1 32
#define NE_PAIRS (N_NODES / 3)  // 16666
#define FULLMASK 0xffffffffu

// ---------------- scratch (device globals: no runtime alloc allowed) ----------------
__device__ __half g_f0h[N_NODES * F0];   // layer0 projected features (fp16)
__device__ float g_h[N_NODES * F0];      // elu(gat0 out)
__device__ float g_el0[N_NODES * NH0];
__device__ float g_er0[N_NODES * NH0];
__device__ __half g_f1h[N_NODES * F1];   // layer1 projected features (fp16)
__device__ float g_el1[N_NODES];
__device__ float g_er1[N_NODES];
__device__ float g_h1[N_NODES * F1];
__device__ int   g_cnt[N_NODES];
__device__ int   g_rowptr[N_NODES + 1];
__device__ int   g_cur[N_NODES];
__device__ int   g_esrc[E_EDGES];

// ---------------- CSR build ----------------
__global__ void k_zero_cnt() {
    int i = blockIdx.x * blockDim.x + threadIdx.x;
    if (i < N_NODES) g_cnt[i] = 0;
}

__global__ void k_count(const int* __restrict__ dst) {
    int e = blockIdx.x * blockDim.x + threadIdx.x;
    if (e < E_EDGES) atomicAdd(&g_cnt[dst[e]], 1);
}

__global__ void k_scan() {
    const int T = 1024;
    int tid = threadIdx.x;
    int chunk = (N_NODES + T - 1) / T;
    int beg = tid * chunk;
    int end = beg + chunk; if (end > N_NODES) end = N_NODES;
    int s = 0;
    for (int i = beg; i < end; i++) s += g_cnt[i];
    __shared__ int sh[T];
    sh[tid] = s;
    __syncthreads();
    for (int d = 1; d < T; d <<= 1) {
        int v = (tid >= d) ? sh[tid - d] : 0;
        __syncthreads();
        sh[tid] += v;
        __syncthreads();
    }
    int run = sh[tid] - s;
    for (int i = beg; i < end; i++) {
        g_rowptr[i] = run;
        g_cur[i] = run;
        run += g_cnt[i];
    }
    if (tid == T - 1) g_rowptr[N_NODES] = sh[T - 1];
}

__global__ void k_fill(const int* __restrict__ src, const int* __restrict__ dst) {
    int e = blockIdx.x * blockDim.x + threadIdx.x;
    if (e < E_EDGES) {
        int p = atomicAdd(&g_cur[dst[e]], 1);
        g_esrc[p] = src[e];
    }
}

// ---------------- tf32 tensor-core GEMM + fused attention scores ----------------
__device__ __forceinline__ uint32_t f2tf(float f) {
    uint32_t r;
    asm("cvt.rna.tf32.f32 %0, %1;" : "=r"(r) : "f"(f));
    return r;
}

__device__ __forceinline__ void mma_tf32(float* d, const uint32_t* a, const uint32_t* b) {
    asm volatile(
        "mma.sync.aligned.m16n8k8.row.col.f32.tf32.tf32.f32 "
        "{%0,%1,%2,%3},{%4,%5,%6,%7},{%8,%9},{%0,%1,%2,%3};\n"
        : "+f"(d[0]), "+f"(d[1]), "+f"(d[2]), "+f"(d[3])
        : "r"(a[0]), "r"(a[1]), "r"(a[2]), "r"(a[3]), "r"(b[0]), "r"(b[1]));
}

// C(MxNc) = A(MxK) @ B(KxNc), tf32 inputs, fp32 accumulate.
// HALF_OUT: C stored as __half. SCORES: fused el/er epilogue (needs WN==32).
template <int BM, int BN, int BK, int WM, int WN, int NH, bool SCORES, bool HALF_OUT>
__global__ void k_gemm_tf32(const float* __restrict__ A, const float* __restrict__ B,
                            void* __restrict__ Cv, int M, int Nc, int K,
                            const float* __restrict__ al, const float* __restrict__ ar,
                            float* __restrict__ el, float* __restrict__ er) {
    constexpr int WARPS_M = BM / WM;
    constexpr int WARPS_N = BN / WN;
    constexpr int THREADS = WARPS_M * WARPS_N * 32;
    constexpr int MT = WM / 16;
    constexpr int NT = WN / 8;
    constexpr int AP = BK + 4;
    constexpr int BP = BN + 8;

    __shared__ uint32_t As[BM][AP];
    __shared__ uint32_t Bs[BK][BP];

    const int tid = threadIdx.x;
    const int wid = tid >> 5, lane = tid & 31;
    const int wm = (wid / WARPS_N) * WM;
    const int wn = (wid % WARPS_N) * WN;
    const int g = lane >> 2, t = lane & 3;
    const int row0 = blockIdx.y * BM, col0 = blockIdx.x * BN;

    float acc[MT][NT][4];
#pragma unroll
    for (int mt = 0; mt < MT; mt++)
#pragma unroll
        for (int nt = 0; nt < NT; nt++)
#pragma unroll
            for (int j = 0; j < 4; j++) acc[mt][nt][j] = 0.f;

    constexpr int A_CG = BK / 4;
    constexpr int A_RPP = THREADS / A_CG;
    constexpr int NB4 = BN / 4;
    constexpr int B_RPP = THREADS / NB4;

    for (int k0 = 0; k0 < K; k0 += BK) {
#pragma unroll
        for (int i = 0; i < BM / A_RPP; i++) {
            int r = (tid / A_CG) + i * A_RPP;
            int c = (tid % A_CG) * 4;
            int gr = row0 + r;
            float4 v = make_float4(0.f, 0.f, 0.f, 0.f);
            if (gr < M) v = *(const float4*)&A[(long)gr * K + k0 + c];
            As[r][c + 0] = f2tf(v.x);
            As[r][c + 1] = f2tf(v.y);
            As[r][c + 2] = f2tf(v.z);
            As[r][c + 3] = f2tf(v.w);
        }
#pragma unroll
        for (int i = 0; i < BK / B_RPP; i++) {
            int r = tid / NB4 + i * B_RPP;
            int c = (tid % NB4) * 4;
            float4 v = *(const float4*)&B[(long)(k0 + r) * Nc + col0 + c];
            Bs[r][c + 0] = f2tf(v.x);
            Bs[r][c + 1] = f2tf(v.y);
            Bs[r][c + 2] = f2tf(v.z);
            Bs[r][c + 3] = f2tf(v.w);
        }
        __syncthreads();

#pragma unroll
        for (int ks = 0; ks < BK / 8; ks++) {
            const int k8 = ks * 8;
            uint32_t af[MT][4], bf[NT][2];
#pragma unroll
            for (int mt = 0; mt < MT; mt++) {
                int r = wm + mt * 16;
                af[mt][0] = As[r + g][k8 + t];
                af[mt][1] = As[r + g + 8][k8 + t];
                af[mt][2] = As[r + g][k8 + t + 4];
                af[mt][3] = As[r + g + 8][k8 + t + 4];
            }
#pragma unroll
            for (int nt = 0; nt < NT; nt++) {
                int c = wn + nt * 8 + g;
                bf[nt][0] = Bs[k8 + t][c];
                bf[nt][1] = Bs[k8 + t + 4][c];
            }
#pragma unroll
            for (int mt = 0; mt < MT; mt++)
#pragma unroll
                for (int nt = 0; nt < NT; nt++) mma_tf32(acc[mt][nt], af[mt], bf[nt]);
        }
        __syncthreads();
    }

#pragma unroll
    for (int mt = 0; mt < MT; mt++) {
#pragma unroll
        for (int nt = 0; nt < NT; nt++) {
            int mr = row0 + wm + mt * 16 + g;
            int c = col0 + wn + nt * 8 + 2 * t;
            if (HALF_OUT) {
                __half* C = (__half*)Cv;
                if (mr < M)
                    *(__half2*)&C[(long)mr * Nc + c] = __floats2half2_rn(acc[mt][nt][0], acc[mt][nt][1]);
                if (mr + 8 < M)
                    *(__half2*)&C[(long)(mr + 8) * Nc + c] = __floats2half2_rn(acc[mt][nt][2], acc[mt][nt][3]);
            } else {
                float* C = (float*)Cv;
                if (mr < M)
                    *(float2*)&C[(long)mr * Nc + c] = make_float2(acc[mt][nt][0], acc[mt][nt][1]);
                if (mr + 8 < M)
                    *(float2*)&C[(long)(mr + 8) * Nc + c] = make_float2(acc[mt][nt][2], acc[mt][nt][3]);
            }
        }
    }

    if (SCORES) {
        const int h = (col0 + wn) >> 5;
#pragma unroll
        for (int mt = 0; mt < MT; mt++) {
            float elA = 0.f, erA = 0.f;
            float elB = 0.f, erB = 0.f;
#pragma unroll
            for (int nt = 0; nt < NT; nt++) {
#pragma unroll
                for (int j = 0; j < 2; j++) {
                    int c = nt * 8 + 2 * t + j;
                    float av = al[h * 32 + c];
                    float rv = ar[h * 32 + c];
                    elA += acc[mt][nt][j] * av;
                    erA += acc[mt][nt][j] * rv;
                    elB += acc[mt][nt][2 + j] * av;
                    erB += acc[mt][nt][2 + j] * rv;
                }
            }
#pragma unroll
            for (int o = 1; o < 4; o <<= 1) {
                elA += __shfl_xor_sync(FULLMASK, elA, o);
                erA += __shfl_xor_sync(FULLMASK, erA, o);
                elB += __shfl_xor_sync(FULLMASK, elB, o);
                erB += __shfl_xor_sync(FULLMASK, erB, o);
            }
            if (t == 0) {
                int r = row0 + wm + mt * 16 + g;
                if (r < M) { el[r * NH + h] = elA; er[r * NH + h] = erA; }
                if (r + 8 < M) { el[(r + 8) * NH + h] = elB; er[(r + 8) * NH + h] = erB; }
            }
        }
    }
}

// ---------------- layer-0 aggregation (×4-unrolled gather, MLP=4) ----------------
// warp per dst node; lane l owns dims [l*8, l*8+8) — all within head l/4.
__global__ void k_agg0(const float* __restrict__ b0) {
    __shared__ float swW[8][32 * 9];
    __shared__ float swS[8][8];

    int gt = blockIdx.x * blockDim.x + threadIdx.x;
    int n = gt >> 5, lane = gt & 31;
    int warp = threadIdx.x >> 5;
    if (n >= N_NODES) return;
    int beg = g_rowptr[n], end = g_rowptr[n + 1];
    int deg = end - beg;
    const int hsel = lane >> 2;

    float er[NH0];
    {
        const float4* erp = (const float4*)&g_er0[n * NH0];
        float4 e0 = erp[0], e1 = erp[1];
        er[0] = e0.x; er[1] = e0.y; er[2] = e0.z; er[3] = e0.w;
        er[4] = e1.x; er[5] = e1.y; er[6] = e1.z; er[7] = e1.w;
    }

    float acc[8];
#pragma unroll
    for (int k = 0; k < 8; k++) acc[k] = 0.f;
    float ssum[NH0];
#pragma unroll
    for (int h = 0; h < NH0; h++) ssum[h] = 0.f;

    for (int base = 0; base < deg; base += 32) {
        int i = base + lane;
        int s = 0;                        // pad: row 0 with weight 0
        float w[NH0];
#pragma unroll
        for (int h = 0; h < NH0; h++) w[h] = 0.f;
        if (i < deg) {
            s = g_esrc[beg + i];
            const float4* elp = (const float4*)&g_el0[s * NH0];
            float4 e0 = elp[0], e1 = elp[1];
            float ev[NH0] = {e0.x, e0.y, e0.z, e0.w, e1.x, e1.y, e1.z, e1.w};
#pragma unroll
            for (int h = 0; h < NH0; h++) {
                float e = ev[h] + er[h];
                e = (e > 0.f) ? e : 0.2f * e;
                float ww = __expf(e);
                w[h] = ww;
                ssum[h] += ww;
            }
        }
#pragma unroll
        for (int h = 0; h < NH0; h++) swW[warp][lane * 9 + h] = w[h];
        __syncwarp();

        int cnt = deg - base; if (cnt > 32) cnt = 32;
        int cnt4 = (cnt + 3) & ~3;        // padded lanes have w=0, s=0 (safe)
        for (int j = 0; j < cnt4; j += 4) {
            int s0 = __shfl_sync(FULLMASK, s, j + 0);
            int s1 = __shfl_sync(FULLMASK, s, j + 1);
            int s2 = __shfl_sync(FULLMASK, s, j + 2);
            int s3 = __shfl_sync(FULLMASK, s, j + 3);
            float w0 = swW[warp][(j + 0) * 9 + hsel];
            float w1 = swW[warp][(j + 1) * 9 + hsel];
            float w2 = swW[warp][(j + 2) * 9 + hsel];
            float w3 = swW[warp][(j + 3) * 9 + hsel];
            uint4 r0 = *(const uint4*)&g_f0h[s0 * F0 + lane * 8];
            uint4 r1 = *(const uint4*)&g_f0h[s1 * F0 + lane * 8];
            uint4 r2 = *(const uint4*)&g_f0h[s2 * F0 + lane * 8];
            uint4 r3 = *(const uint4*)&g_f0h[s3 * F0 + lane * 8];
#pragma unroll
            for (int q = 0; q < 4; q++) {
                float2 pa = __half22float2(((const __half2*)&r0)[q]);
                acc[2 * q + 0] += w0 * pa.x; acc[2 * q + 1] += w0 * pa.y;
            }
#pragma unroll
            for (int q = 0; q < 4; q++) {
                float2 pa = __half22float2(((const __half2*)&r1)[q]);
                acc[2 * q + 0] += w1 * pa.x; acc[2 * q + 1] += w1 * pa.y;
            }
#pragma unroll
            for (int q = 0; q < 4; q++) {
                float2 pa = __half22float2(((const __half2*)&r2)[q]);
                acc[2 * q + 0] += w2 * pa.x; acc[2 * q + 1] += w2 * pa.y;
            }
#pragma unroll
            for (int q = 0; q < 4; q++) {
                float2 pa = __half22float2(((const __half2*)&r3)[q]);
                acc[2 * q + 0] += w3 * pa.x; acc[2 * q + 1] += w3 * pa.y;
            }
        }
        __syncwarp();
    }

#pragma unroll
    for (int h = 0; h < NH0; h++) {
        float r = ssum[h];
#pragma unroll
        for (int o = 16; o; o >>= 1) r += __shfl_xor_sync(FULLMASK, r, o);
        if (lane == h) swS[warp][h] = r;
    }
    __syncwarp();
    float inv = (deg > 0) ? (1.f / swS[warp][hsel]) : 0.f;

    const float4* bp = (const float4*)&b0[lane * 8];
    float4 b_lo = bp[0], b_hi = bp[1];
    float bb[8] = {b_lo.x, b_lo.y, b_lo.z, b_lo.w, b_hi.x, b_hi.y, b_hi.z, b_hi.w};
    float v[8];
#pragma unroll
    for (int k = 0; k < 8; k++) {
        float t = acc[k] * inv + bb[k];
        v[k] = (t > 0.f) ? t : expm1f(t);
    }
    float4* op = (float4*)&g_h[n * F0 + lane * 8];
    op[0] = make_float4(v[0], v[1], v[2], v[3]);
    op[1] = make_float4(v[4], v[5], v[6], v[7]);
}

// ---------------- layer-1 aggregation (×4-unrolled, fp16 gather) ----------------
__global__ void k_agg1(const float* __restrict__ b1) {
    int g = blockIdx.x * blockDim.x + threadIdx.x;
    int n = g >> 5, lane = g & 31;
    if (n >= N_NODES) return;
    int beg = g_rowptr[n], end = g_rowptr[n + 1];
    int deg = end - beg;
    float er = g_er1[n];

    float acc = 0.f, ssum = 0.f;
    for (int base = 0; base < deg; base += 32) {
        int i = base + lane;
        int s = 0;
        float w = 0.f;
        if (i < deg) {
            s = g_esrc[beg + i];
            float e = g_el1[s] + er;
            e = (e > 0.f) ? e : 0.2f * e;
            w = __expf(e);
            ssum += w;
        }
        int cnt = deg - base; if (cnt > 32) cnt = 32;
        int cnt4 = (cnt + 3) & ~3;
        for (int j = 0; j < cnt4; j += 4) {
            int s0 = __shfl_sync(FULLMASK, s, j + 0);
            int s1 = __shfl_sync(FULLMASK, s, j + 1);
            int s2 = __shfl_sync(FULLMASK, s, j + 2);
            int s3 = __shfl_sync(FULLMASK, s, j + 3);
            float w0 = __shfl_sync(FULLMASK, w, j + 0);
            float w1 = __shfl_sync(FULLMASK, w, j + 1);
            float w2 = __shfl_sync(FULLMASK, w, j + 2);
            float w3 = __shfl_sync(FULLMASK, w, j + 3);
            float f0v = __half2float(g_f1h[s0 * F1 + lane]);
            float f1v = __half2float(g_f1h[s1 * F1 + lane]);
            float f2v = __half2float(g_f1h[s2 * F1 + lane]);
            float f3v = __half2float(g_f1h[s3 * F1 + lane]);
            acc += w0 * f0v + w1 * f1v + w2 * f2v + w3 * f3v;
        }
    }
#pragma unroll
    for (int o = 16; o; o >>= 1) ssum += __shfl_xor_sync(FULLMASK, ssum, o);

    float v = (deg > 0) ? (acc / ssum) : 0.f;
    g_h1[n * F1 + lane] = v + b1[lane];
}

// ---------------- link predictor MLP: warp per pair ----------------
__global__ void k_pred(const float* __restrict__ P1, const float* __restrict__ pb1,
                       const float* __restrict__ P2, const float* __restrict__ pb2,
                       const float* __restrict__ P3, const float* __restrict__ pb3,
                       float* __restrict__ out) {
    __shared__ float sP1[1024], sP2[1024], sP3[32], sb1[32], sb2[32];
    for (int i = threadIdx.x; i < 1024; i += blockDim.x) { sP1[i] = P1[i]; sP2[i] = P2[i]; }
    if (threadIdx.x < 32) {
        sP3[threadIdx.x] = P3[threadIdx.x];
        sb1[threadIdx.x] = pb1[threadIdx.x];
        sb2[threadIdx.x] = pb2[threadIdx.x];
    }
    __syncthreads();

    int g = blockIdx.x * blockDim.x + threadIdx.x;
    int w = g >> 5, lane = g & 31;
    if (w >= 2 * NE_PAIRS) return;
    int neg = (w >= NE_PAIRS) ? 1 : 0;
    int i = w - neg * NE_PAIRS;

    float a = g_h1[i * F1 + lane];
    int dst_row = neg ? (2 * NE_PAIRS + i) : (NE_PAIRS + i);
    float z = a * g_h1[dst_row * F1 + lane];

    float y = sb1[lane];
#pragma unroll
    for (int d = 0; d < 32; d++) {
        float zd = __shfl_sync(FULLMASK, z, d);
        y += zd * sP1[d * 32 + lane];
    }
    y = fmaxf(y, 0.f);
    float y2 = sb2[lane];
#pragma unroll
    for (int d = 0; d < 32; d++) {
        float yd = __shfl_sync(FULLMASK, y, d);
        y2 += yd * sP2[d * 32 + lane];
    }
    y2 = fmaxf(y2, 0.f);
    float t = y2 * sP3[lane];
#pragma unroll
    for (int o = 16; o; o >>= 1) t += __shfl_xor_sync(FULLMASK, t, o);
    if (lane == 0) out[neg * NE_PAIRS + i] = t + pb3[0];
}

// ---------------- launch ----------------
extern "C" void kernel_launch(void* const* d_in, const int* in_sizes, int n_in,
                              void* d_out, int out_size) {
    const float* x   = (const float*)d_in[0];
    const int*   src = (const int*)d_in[1];
    const int*   dst = (const int*)d_in[2];
    const float* W0  = (const float*)d_in[4];
    const float* al0 = (const float*)d_in[5];
    const float* ar0 = (const float*)d_in[6];
    const float* b0  = (const float*)d_in[7];
    const float* W1  = (const float*)d_in[8];
    const float* al1 = (const float*)d_in[9];
    const float* ar1 = (const float*)d_in[10];
    const float* b1  = (const float*)d_in[11];
    const float* P1  = (const float*)d_in[12];
    const float* pb1 = (const float*)d_in[13];
    const float* P2  = (const float*)d_in[14];
    const float* pb2 = (const float*)d_in[15];
    const float* P3  = (const float*)d_in[16];
    const float* pb3 = (const float*)d_in[17];
    float* out = (float*)d_out;

    void *p_f0h, *p_f1h;
    float *p_h, *p_el0, *p_er0, *p_el1, *p_er1;
    cudaGetSymbolAddress(&p_f0h, g_f0h);
    cudaGetSymbolAddress(&p_f1h, g_f1h);
    cudaGetSymbolAddress((void**)&p_h, g_h);
    cudaGetSymbolAddress((void**)&p_el0, g_el0);
    cudaGetSymbolAddress((void**)&p_er0, g_er0);
    cudaGetSymbolAddress((void**)&p_el1, g_el1);
    cudaGetSymbolAddress((void**)&p_er1, g_er1);

    static cudaStream_t sB = nullptr;
    static cudaEvent_t evFork = nullptr, evJoin = nullptr;
    if (sB == nullptr) {
        cudaStreamCreateWithFlags(&sB, cudaStreamNonBlocking);
        cudaEventCreateWithFlags(&evFork, cudaEventDisableTiming);
        cudaEventCreateWithFlags(&evJoin, cudaEventDisableTiming);
    }

    cudaEventRecord(evFork, 0);
    cudaStreamWaitEvent(sB, evFork, 0);

    // branch B: CSR by dst
    k_zero_cnt<<<(N_NODES + 255) / 256, 256, 0, sB>>>();
    k_count<<<(E_EDGES + 255) / 256, 256, 0, sB>>>(dst);
    k_scan<<<1, 1024, 0, sB>>>();
    k_fill<<<(E_EDGES + 255) / 256, 256, 0, sB>>>(src, dst);
    cudaEventRecord(evJoin, sB);

    // branch A: layer-0 GEMM (tf32) + fused scores, fp16 out
    k_gemm_tf32<128, 64, 32, 32, 32, NH0, true, true>
        <<<dim3(F0 / 64, (N_NODES + 127) / 128), 256>>>(
            x, W0, p_f0h, N_NODES, F0, DIN, al0, ar0, p_el0, p_er0);

    cudaStreamWaitEvent(0, evJoin, 0);

    k_agg0<<<(N_NODES + 7) / 8, 256>>>(b0);

    // layer 1: tf32 GEMM + fused scores, fp16 out
    k_gemm_tf32<128, 32, 32, 16, 32, 1, true, true>
        <<<dim3(1, (N_NODES + 127) / 128), 256>>>(
            p_h, W1, p_f1h, N_NODES, F1, F0, al1, ar1, p_el1, p_er1);
    k_agg1<<<(N_NODES * 32 + 255) / 256, 256>>>(b1);

    // predictor
    k_pred<<<(2 * NE_PAIRS * 32 + 255) / 256, 256>>>(P1, pb1, P2, pb2, P3, pb3, out);
}